// round 6
// baseline (speedup 1.0000x reference)
#include <cuda_runtime.h>
#include <stdint.h>

#define D       256
#define MITEMS  16
#define TPB     128
#define RPT     2
#define ROWS    256          // rows per block
#define CHUNK   16           // dims per pipeline stage
#define NCH     16
#define QSTR    20           // q smem row stride (floats): 16B-aligned, LDS.128 conflict-free
#define QBUF    (ROWS * QSTR)        // 5120 floats per buffer
#define SM_MT   (2 * QBUF)           // mem_t offset: 10240
#define WSTR    20                   // W row stride (aliases qs buf0: 256*20 = 5120 = QBUF)
#define SMEM_FLOATS (SM_MT + MITEMS * D)   // 14336 floats = 56 KB
#define SMEM_BYTES  (SMEM_FLOATS * 4)
#define NEG_BIG (-1e30f)

typedef unsigned long long u64;

__device__ __forceinline__ u64 pack2(float lo, float hi) {
    u64 r; asm("mov.b64 %0, {%1, %2};" : "=l"(r) : "f"(lo), "f"(hi)); return r;
}
__device__ __forceinline__ void unpack2(u64 v, float& lo, float& hi) {
    asm("mov.b64 {%0, %1}, %2;" : "=f"(lo), "=f"(hi) : "l"(v));
}
#define FMA2(d, a, b) asm("fma.rn.f32x2 %0, %1, %2, %0;" : "+l"(d) : "l"(a), "l"(b))
#define CP16(dst, src) \
    asm volatile("cp.async.cg.shared.global [%0], [%1], 16;" :: "r"(dst), "l"(src))
#define CPCOMMIT() asm volatile("cp.async.commit_group;")
#define CPWAIT(n)  asm volatile("cp.async.wait_group %0;" :: "n"(n))

__global__ void __launch_bounds__(TPB, 4) epm_kernel(
    const float* __restrict__ q,
    const float* __restrict__ mem,
    float* __restrict__ out_ret,
    float* __restrict__ out_max,
    int nrows)
{
    extern __shared__ __align__(16) float sh[];
    float* qs    = sh;                 // 2 buffers of ROWS x QSTR
    float* mem_t = sh + SM_MT;         // [dim][16 items]
    float* Wm    = sh;                 // aliases qs buf0 (dead after dot)

    const int tid = threadIdx.x;
    const int blockRow = blockIdx.x * ROWS;
    const int nr1 = nrows - 1;
    const uint32_t qs_s = (uint32_t)__cvta_generic_to_shared(qs);

    // cp.async lane mapping: each chunk = 256 rows x 64B = 128 thr x 8 CP16
    const int rsub = tid >> 2;    // 0..31
    const int sub  = tid & 3;     // 16B slot within a row's 64B chunk segment

    // ---- issue chunk 0 immediately (overlap DRAM latency with mem_t build) ----
    {
        #pragma unroll
        for (int j = 0; j < 8; j++) {
            int rl = rsub + 32 * j;
            int rg = blockRow + rl; rg = rg < nr1 ? rg : nr1;
            const float* src = q + (size_t)rg * D + sub * 4;
            uint32_t dst = qs_s + (uint32_t)(rl * QSTR + sub * 4) * 4u;
            CP16(dst, src);
        }
        CPCOMMIT();
    }

    // ---- build mem_t [dim][item] via two-step transpose (temp in qs buf1) ----
    {
        float* tmp = qs + QBUF;                 // 16 x 257 = 4112 floats <= 5120
        #pragma unroll
        for (int i = 0; i < (MITEMS * D) / TPB; i++) {   // 32 coalesced LDG
            int idx = tid + TPB * i;
            tmp[(idx >> 8) * 257 + (idx & 255)] = mem[idx];
        }
        __syncthreads();
        const int m0 = tid & 15;
        const int c0 = tid >> 4;                // 0..7
        #pragma unroll
        for (int i = 0; i < 32; i++) {
            int c = c0 + 8 * i;
            mem_t[c * MITEMS + m0] = tmp[m0 * 257 + c];
        }
        __syncthreads();                        // tmp reads done -> buf1 reusable
    }

    // ---- issue chunk 1 into buf1 ----
    {
        #pragma unroll
        for (int j = 0; j < 8; j++) {
            int rl = rsub + 32 * j;
            int rg = blockRow + rl; rg = rg < nr1 ? rg : nr1;
            const float* src = q + (size_t)rg * D + CHUNK + sub * 4;
            uint32_t dst = qs_s + (uint32_t)(QBUF + rl * QSTR + sub * 4) * 4u;
            CP16(dst, src);
        }
        CPCOMMIT();
    }

    // ---- dot mainloop: 2 rows/thread, item-pair-packed f32x2 ----
    u64 acc[RPT][8];
    float ssq[RPT];
    #pragma unroll
    for (int r = 0; r < RPT; r++) {
        ssq[r] = 0.0f;
        #pragma unroll
        for (int p = 0; p < 8; p++) acc[r][p] = 0ull;
    }

    #pragma unroll 1
    for (int ct = 0; ct < NCH; ct++) {
        if (ct + 1 < NCH) { CPWAIT(1); } else { CPWAIT(0); }
        __syncthreads();                        // chunk ct visible to all

        const float* qb = qs + (ct & 1) * QBUF;
        #pragma unroll
        for (int gr = 0; gr < 4; gr++) {        // 4-dim groups
            float qa[RPT][4];
            #pragma unroll
            for (int r = 0; r < RPT; r++) {
                float4 f = *(const float4*)(qb + (tid + 128 * r) * QSTR + 4 * gr);
                qa[r][0] = f.x; qa[r][1] = f.y; qa[r][2] = f.z; qa[r][3] = f.w;
            }
            #pragma unroll
            for (int c = 0; c < 4; c++) {
                const ulonglong2* mt =
                    (const ulonglong2*)(mem_t + (ct * CHUNK + gr * 4 + c) * MITEMS);
                ulonglong2 v0 = mt[0], v1 = mt[1], v2 = mt[2], v3 = mt[3];
                u64 mp[8] = {v0.x, v0.y, v1.x, v1.y, v2.x, v2.y, v3.x, v3.y};
                #pragma unroll
                for (int r = 0; r < RPT; r++) {
                    float qv = qa[r][c];
                    u64 qq = pack2(qv, qv);
                    ssq[r] = fmaf(qv, qv, ssq[r]);
                    #pragma unroll
                    for (int p = 0; p < 8; p++) FMA2(acc[r][p], mp[p], qq);
                }
            }
        }
        __syncthreads();                        // buf ct&1 reads done everywhere
        if (ct + 2 < NCH) {                     // refill the just-freed buffer
            #pragma unroll
            for (int j = 0; j < 8; j++) {
                int rl = rsub + 32 * j;
                int rg = blockRow + rl; rg = rg < nr1 ? rg : nr1;
                const float* src = q + (size_t)rg * D + (ct + 2) * CHUNK + sub * 4;
                uint32_t dst = qs_s + (uint32_t)((ct & 1) * QBUF + rl * QSTR + sub * 4) * 4u;
                CP16(dst, src);
            }
            CPCOMMIT();
        }
    }

    // ---- epilogue: 2 rows/thread -> W rows (stride 20, aliases buf0) ----
    #pragma unroll
    for (int g = 0; g < RPT; g++) {
        float s[MITEMS];
        #pragma unroll
        for (int p = 0; p < 8; p++) { unpack2(acc[g][p], s[2 * p], s[2 * p + 1]); }
        float inv = rsqrtf(fmaxf(ssq[g], 1e-24f)) * 10.0f;  // (1/|q|)/tau; mem unit-norm
        #pragma unroll
        for (int m = 0; m < MITEMS; m++) s[m] *= inv;

        float bw[4]; int bi[4];
        #pragma unroll
        for (int k = 0; k < 4; k++) {
            float best = NEG_BIG; int b = 0;
            #pragma unroll
            for (int m = 0; m < MITEMS; m++)
                if (s[m] > best) { best = s[m]; b = m; }   // strict > : first-index ties
            bw[k] = best; bi[k] = b;
            #pragma unroll
            for (int m = 0; m < MITEMS; m++)
                s[m] = (m == b) ? NEG_BIG : s[m];
        }
        float e1 = __expf(bw[1] - bw[0]);
        float e2 = __expf(bw[2] - bw[0]);
        float e3 = __expf(bw[3] - bw[0]);
        float rden = 1.0f / (1.0f + e1 + e2 + e3);

        int rl = tid + 128 * g;
        float* Wr = Wm + rl * WSTR;
        #pragma unroll
        for (int m = 0; m < MITEMS; m++) Wr[m] = 0.0f;
        Wr[bi[0]] = rden;
        Wr[bi[1]] = e1 * rden;
        Wr[bi[2]] = e2 * rden;
        Wr[bi[3]] = e3 * rden;

        int row_g = blockRow + rl;
        if (row_g < nrows) out_max[row_g] = bw[0];
    }
    __syncthreads();

    // ---- dense blend from registers, two half-passes to cap reg pressure ----
    const int wid  = tid >> 5;
    const int lane = tid & 31;
    const ulonglong2* mg = (const ulonglong2*)mem;    // 64 x 16B per item row

    #pragma unroll 1
    for (int p = 0; p < 2; p++) {
        ulonglong2 V[MITEMS];                         // half the bank, register-resident
        #pragma unroll
        for (int m = 0; m < MITEMS; m++)
            V[m] = mg[m * (D / 4) + p * 32 + lane];

        #pragma unroll 2
        for (int j = 0; j < ROWS / 4; j++) {          // 64 rows per warp
            int rl = wid * (ROWS / 4) + j;
            int row_g = blockRow + rl;
            const float4* Wp = (const float4*)(Wm + rl * WSTR);   // broadcast
            float4 w0 = Wp[0], w1 = Wp[1], w2 = Wp[2], w3 = Wp[3];
            float wv[16] = {w0.x, w0.y, w0.z, w0.w, w1.x, w1.y, w1.z, w1.w,
                            w2.x, w2.y, w2.z, w2.w, w3.x, w3.y, w3.z, w3.w};
            u64 o0 = 0ull, o1 = 0ull;
            #pragma unroll
            for (int m = 0; m < MITEMS; m++) {
                u64 wm = pack2(wv[m], wv[m]);
                FMA2(o0, V[m].x, wm);
                FMA2(o1, V[m].y, wm);
            }
            if (row_g < nrows) {
                ulonglong2 r0; r0.x = o0; r0.y = o1;
                ((ulonglong2*)(out_ret + (size_t)row_g * D))[p * 32 + lane] = r0;
            }
        }
    }
}

extern "C" void kernel_launch(void* const* d_in, const int* in_sizes, int n_in,
                              void* d_out, int out_size)
{
    const float* q   = (const float*)d_in[0];
    const float* mem = (const float*)d_in[1];
    int nrows = in_sizes[0] / D;              // 131072
    float* out_ret = (float*)d_out;
    float* out_max = out_ret + (size_t)nrows * D;

    cudaFuncSetAttribute(epm_kernel,
                         cudaFuncAttributeMaxDynamicSharedMemorySize, SMEM_BYTES);

    int grid = (nrows + ROWS - 1) / ROWS;     // 512
    epm_kernel<<<grid, TPB, SMEM_BYTES>>>(q, mem, out_ret, out_max, nrows);
}